// round 11
// baseline (speedup 1.0000x reference)
#include <cuda_runtime.h>
#include <cuda_fp16.h>

#define N_NODES 100000
#define N_EDGES 1000000
#define D_FEAT 64

// Scratch (allocation-free rule: __device__ globals)
__device__ __half g_hfeats[N_NODES * D_FEAT];   // 12.8 MB fp16 feature table
__device__ __half g_exh[N_EDGES];               // 2 MB per-edge ex (fp16)
__device__ float  g_sum[N_NODES];

__device__ __forceinline__ unsigned pack_h2(float a, float b) {
    half2 h = __floats2half2_rn(a, b);
    return *reinterpret_cast<unsigned*>(&h);
}

__device__ __forceinline__ float dot8h(float4 a, float4 b) {
    const half2* pa = reinterpret_cast<const half2*>(&a);
    const half2* pb = reinterpret_cast<const half2*>(&b);
    float acc = 0.0f;
#pragma unroll
    for (int i = 0; i < 4; i++) {
        float2 fa = __half22float2(pa[i]);
        float2 fb = __half22float2(pb[i]);
        acc = fmaf(fa.x, fb.x, acc);
        acc = fmaf(fa.y, fb.y, acc);
    }
    return acc;
}

// ---------------------------------------------------------------------------
// Kernel 1: fp32->fp16 convert (8 elems/thread, 800k threads) + zero g_sum.
// Default-cached loads: the full working set (~53MB) fits in L2 across graph
// replays, so feats stays L2-resident between timed replays. (__ldcs here was
// evicting it and forcing a DRAM re-pull every replay.)
// ---------------------------------------------------------------------------
__global__ __launch_bounds__(256)
void convert_kernel(const float* __restrict__ feats) {
    int i = blockIdx.x * blockDim.x + threadIdx.x;        // 8-elem index
    if (i < N_NODES) g_sum[i] = 0.0f;
    if (i >= (N_NODES * D_FEAT) / 8) return;

    const float4* in = reinterpret_cast<const float4*>(feats) + i * 2;
    float4 f0 = __ldg(in);
    float4 f1 = __ldg(in + 1);

    uint4 packed;
    packed.x = pack_h2(f0.x, f0.y);
    packed.y = pack_h2(f0.z, f0.w);
    packed.z = pack_h2(f1.x, f1.y);
    packed.w = pack_h2(f1.z, f1.w);
    reinterpret_cast<uint4*>(g_hfeats)[i] = packed;
}

// ---------------------------------------------------------------------------
// Kernel 2 (PDL secondary): prefetch src/dst indices BEFORE the grid
// dependency sync (overlaps the 8MB index read + launch ramp with convert's
// tail), then gather fp16 rows, dot, ex = exp(exp(-0.01|dot|)), atomicAdd.
// 4 lanes/edge; 128B fp16 row covered by 4 contiguous LDG.128.
// Segment-max pass skipped exactly (softmax shift-invariance; e in (0.6,1]).
// ex rounded to fp16; the SAME rounded value feeds the sum (rounding largely
// cancels in the final ratio).
// ---------------------------------------------------------------------------
__global__ __launch_bounds__(256)
void edge_kernel(const int* __restrict__ src,
                 const int* __restrict__ dst) {
    int tid = blockIdx.x * blockDim.x + threadIdx.x;
    int eid = tid >> 2;      // 4 lanes per edge
    int sub = tid & 3;
    if (eid >= N_EDGES) return;

    // Independent of convert's output — issue before the dependency sync.
    int s = __ldg(src + eid);
    int d = __ldg(dst + eid);

    cudaGridDependencySynchronize();   // wait for convert's writes to be visible

    const float4* fs = reinterpret_cast<const float4*>(g_hfeats + (size_t)s * D_FEAT);
    const float4* fd = reinterpret_cast<const float4*>(g_hfeats + (size_t)d * D_FEAT);

    float4 a0 = fs[sub];
    float4 a1 = fs[sub + 4];
    float4 b0 = fd[sub];
    float4 b1 = fd[sub + 4];

    float acc = dot8h(a0, b0) + dot8h(a1, b1);

    acc += __shfl_down_sync(0xFFFFFFFFu, acc, 2);
    acc += __shfl_down_sync(0xFFFFFFFFu, acc, 1);

    if (sub == 0) {
        float e  = __expf(-0.01f * fabsf(acc));   // in (0.6, 1]
        float ex = __expf(e);                     // in (1.9, 2.8)
        __half h = __float2half_rn(ex);
        g_exh[eid] = h;
        atomicAdd(&g_sum[d], __half2float(h));
    }
}

// ---------------------------------------------------------------------------
// Kernel 3 (PDL secondary): prefetch dst pair before the sync, then
// out[e] = ex[e] / sum[dst[e]], 2 edges/thread. Output store is streaming
// (write-once, never re-read — keep it out of L2 to protect residency).
// ---------------------------------------------------------------------------
__global__ __launch_bounds__(256)
void div_kernel(const int* __restrict__ dst,
                float* __restrict__ out) {
    int i = blockIdx.x * blockDim.x + threadIdx.x;        // pair index
    if (i >= N_EDGES / 2) return;

    // Independent of edge's output — issue before the dependency sync.
    int2 d2 = __ldg(reinterpret_cast<const int2*>(dst) + i);

    cudaGridDependencySynchronize();   // wait for edge's g_exh / g_sum

    half2 eh = reinterpret_cast<const half2*>(g_exh)[i];
    float s0 = g_sum[d2.x];
    float s1 = g_sum[d2.y];
    float2 ef = __half22float2(eh);

    float2 o;
    o.x = ef.x / s0;
    o.y = ef.y / s1;
    __stcs(reinterpret_cast<float2*>(out) + i, o);
}

// ---------------------------------------------------------------------------
static void launch_pdl(void* func, dim3 grid, dim3 block,
                       void** args) {
    cudaLaunchConfig_t cfg = {};
    cfg.gridDim = grid;
    cfg.blockDim = block;
    cfg.dynamicSmemBytes = 0;
    cfg.stream = 0;
    cudaLaunchAttribute attr[1];
    attr[0].id = cudaLaunchAttributeProgrammaticStreamSerialization;
    attr[0].val.programmaticStreamSerializationAllowed = 1;
    cfg.attrs = attr;
    cfg.numAttrs = 1;
    cudaLaunchKernelExC(&cfg, func, args);
}

extern "C" void kernel_launch(void* const* d_in, const int* in_sizes, int n_in,
                              void* d_out, int out_size) {
    const float* feats = (const float*)d_in[0];
    const int*   src   = (const int*)d_in[1];
    const int*   dst   = (const int*)d_in[2];
    float* out = (float*)d_out;

    convert_kernel<<<((N_NODES * D_FEAT / 8) + 255) / 256, 256>>>(feats);

    {
        void* args[2] = { (void*)&src, (void*)&dst };
        launch_pdl((void*)edge_kernel,
                   dim3((N_EDGES * 4 + 255) / 256), dim3(256), args);
    }
    {
        void* args[2] = { (void*)&dst, (void*)&out };
        launch_pdl((void*)div_kernel,
                   dim3(((N_EDGES / 2) + 255) / 256), dim3(256), args);
    }
}